// round 9
// baseline (speedup 1.0000x reference)
#include <cuda_runtime.h>
#include <cuda_bf16.h>
#include <cstdint>

#define N_NODES 200000
#define N_EDGES 6400000
#define N_LAYERS 3

// Scratch (no cudaMalloc allowed)
__device__ float4 g_T[N_NODES];    // (t0, t1, t2, deg) accumulators
__device__ float  g_A[N_NODES];    // current per-node cumulative scalar
__device__ float  g_q1[N_NODES];   // M @ A_1
__device__ float  g_q2[N_NODES];   // M @ A_2
// per-layer 16 floats: [0..11]=W row, [12]=b, [13]=sA=sum(w[0:4]), [14]=sB=sum(w[4:8])
__device__ float  g_wc[N_LAYERS * 16];

// PDL primitives
__device__ __forceinline__ void pdl_wait() {
    asm volatile("griddepcontrol.wait;" ::: "memory");
}
__device__ __forceinline__ void pdl_trigger() {
    asm volatile("griddepcontrol.launch_dependents;" ::: "memory");
}

// ---------------------------------------------------------------------------
// 1. init: zero T; block 0 also computes per-layer weight constants
// ---------------------------------------------------------------------------
__global__ void init_kernel(const float* __restrict__ W,
                            const float* __restrict__ b,
                            float4* __restrict__ T) {
    int n = blockIdx.x * blockDim.x + threadIdx.x;
    if (blockIdx.x == 0 && threadIdx.x < N_LAYERS) {
        int i = threadIdx.x;
        float sA = 0.f, sB = 0.f;
        #pragma unroll
        for (int j = 0; j < 12; j++) {
            float w = W[i * 12 + j];
            g_wc[i * 16 + j] = w;
            if (j < 4)       sA += w;
            else if (j < 8)  sB += w;
        }
        g_wc[i * 16 + 12] = b[i];
        g_wc[i * 16 + 13] = sA;
        g_wc[i * 16 + 14] = sB;
    }
    if (n < N_NODES)
        T[n] = make_float4(0.f, 0.f, 0.f, 0.f);
    pdl_trigger();
}

// ---------------------------------------------------------------------------
__device__ __forceinline__ void red_add_v4(float4* ptr, float a, float b,
                                           float c, float d) {
    asm volatile("red.global.add.v4.f32 [%0], {%1, %2, %3, %4};"
                 :: "l"(__cvta_generic_to_global(ptr)),
                    "f"(a), "f"(b), "f"(c), "f"(d)
                 : "memory");
}

// ---------------------------------------------------------------------------
// 2. ONE heavy edge pass for all 3 layers, 4 edges per thread:
//    T[dst] += ( ws_l.z0[src] + w_geo_l.(r,rhat)  for l=0..2 , 1 )
//    All loads read pure inputs -> issue BEFORE pdl_wait; only the REDs into
//    T (zeroed by init) must come after the wait.
// ---------------------------------------------------------------------------
__global__ void __launch_bounds__(256)
heavy_edge_kernel(const int4* __restrict__ src4,
                  const int4* __restrict__ dst4,
                  const float4* __restrict__ r4,
                  const float4* __restrict__ rhat4,
                  const float4* __restrict__ z0,
                  float4* __restrict__ T) {
    int t = blockIdx.x * blockDim.x + threadIdx.x;
    if (t >= N_EDGES / 4) { pdl_wait(); pdl_trigger(); return; }

    int4   s  = __ldcs(src4 + t);
    int4   d  = __ldcs(dst4 + t);
    float4 r  = __ldcs(r4   + t);
    float4 h0 = __ldcs(rhat4 + 3 * t + 0);
    float4 h1 = __ldcs(rhat4 + 3 * t + 1);
    float4 h2 = __ldcs(rhat4 + 3 * t + 2);

    float4 zs0 = __ldg(&z0[s.x]);
    float4 zs1 = __ldg(&z0[s.y]);
    float4 zs2 = __ldg(&z0[s.z]);
    float4 zs3 = __ldg(&z0[s.w]);

    pdl_wait();   // init must have zeroed T and written g_wc

    float rr[4]    = {r.x, r.y, r.z, r.w};
    float rh[4][3] = {{h0.x, h0.y, h0.z}, {h0.w, h1.x, h1.y},
                      {h1.z, h1.w, h2.x}, {h2.y, h2.z, h2.w}};
    float4 zs[4]   = {zs0, zs1, zs2, zs3};
    int    dd[4]   = {d.x, d.y, d.z, d.w};

    float tv[4][3];
    #pragma unroll
    for (int l = 0; l < N_LAYERS; l++) {
        const float* wc = g_wc + l * 16;
        float w0 = wc[0], w1 = wc[1], w2 = wc[2], w3 = wc[3];
        float w8 = wc[8], w9 = wc[9], wa = wc[10], wb = wc[11];
        #pragma unroll
        for (int e = 0; e < 4; e++) {
            tv[e][l] = w0 * zs[e].x + w1 * zs[e].y + w2 * zs[e].z + w3 * zs[e].w
                     + w8 * rr[e] + w9 * rh[e][0] + wa * rh[e][1] + wb * rh[e][2];
        }
    }

    #pragma unroll
    for (int e = 0; e < 4; e++)
        red_add_v4(&T[dd[e]], tv[e][0], tv[e][1], tv[e][2], 1.f);

    pdl_trigger();
}

// ---------------------------------------------------------------------------
// 3. Light edge pass, 4 edges per thread: q[dst] += A[src]
//    Stream loads (src/dst) are inputs -> before wait; A-gather and RED after.
// ---------------------------------------------------------------------------
__global__ void __launch_bounds__(256)
light_edge_kernel(const int4* __restrict__ src4,
                  const int4* __restrict__ dst4,
                  const float* __restrict__ A,
                  float* __restrict__ q) {
    int t = blockIdx.x * blockDim.x + threadIdx.x;
    if (t >= N_EDGES / 4) { pdl_wait(); pdl_trigger(); return; }

    int4 s = __ldcs(src4 + t);
    int4 d = __ldcs(dst4 + t);

    pdl_wait();   // A and zeroed q come from the preceding node kernel

    float a0 = __ldg(&A[s.x]);
    float a1 = __ldg(&A[s.y]);
    float a2 = __ldg(&A[s.z]);
    float a3 = __ldg(&A[s.w]);

    atomicAdd(&q[d.x], a0);
    atomicAdd(&q[d.y], a1);
    atomicAdd(&q[d.z], a2);
    atomicAdd(&q[d.w], a3);

    pdl_trigger();
}

// ---------------------------------------------------------------------------
// 4. Node update layer 0: A1 = t0 + deg*(b0 + wd0.z0)   (A0 = 0, q0 = 0)
//    Also zeroes q1 and writes out_x = z0. z0 load is input -> before wait.
// ---------------------------------------------------------------------------
__global__ void node0_kernel(const float4* __restrict__ z0,
                             const float4* __restrict__ T,
                             float* __restrict__ A,
                             float* __restrict__ q1,
                             float4* __restrict__ out) {
    int n = blockIdx.x * blockDim.x + threadIdx.x;
    if (n >= N_NODES) { pdl_wait(); pdl_trigger(); return; }
    float4 z = z0[n];
    pdl_wait();   // T from heavy pass
    const float* wc = g_wc;  // layer 0
    float4 tt = T[n];
    float pd = wc[12] + wc[4]*z.x + wc[5]*z.y + wc[6]*z.z + wc[7]*z.w;
    A[n] = tt.x + tt.w * pd;
    q1[n] = 0.f;
    out[N_NODES + n] = z;     // x output
    pdl_trigger();
}

// ---------------------------------------------------------------------------
// 5. Node update layer 1: A2 = A1 + t1 + sA1*q1 + deg*(b1 + wd1.z0 + sB1*A1)
//    Also zeroes q2.
// ---------------------------------------------------------------------------
__global__ void node_update1_kernel(const float4* __restrict__ z0,
                                    const float4* __restrict__ T,
                                    const float* __restrict__ q,
                                    float* __restrict__ A,
                                    float* __restrict__ q2) {
    int n = blockIdx.x * blockDim.x + threadIdx.x;
    if (n >= N_NODES) { pdl_wait(); pdl_trigger(); return; }
    float4 z = z0[n];
    pdl_wait();   // q1 from light pass 1
    const float* wc = g_wc + 16;  // layer 1
    float4 tt = T[n];
    float  a = A[n];
    float pd = wc[12] + wc[4]*z.x + wc[5]*z.y + wc[6]*z.z + wc[7]*z.w + wc[14]*a;
    A[n] = a + tt.y + wc[13] * q[n] + tt.w * pd;
    q2[n] = 0.f;
    pdl_trigger();
}

// ---------------------------------------------------------------------------
// 6. Node update layer 2 + finalize:
//    A3 = A2 + t2 + sA2*q2 + deg*(b2 + wd2.z0 + sB2*A2);  out_z = z0 + A3
// ---------------------------------------------------------------------------
__global__ void node_update2_final_kernel(const float4* __restrict__ z0,
                                          const float4* __restrict__ T,
                                          const float* __restrict__ q,
                                          const float* __restrict__ A,
                                          float4* __restrict__ out) {
    int n = blockIdx.x * blockDim.x + threadIdx.x;
    if (n >= N_NODES) return;
    float4 z = z0[n];
    pdl_wait();   // q2 from light pass 2
    const float* wc = g_wc + 32;  // layer 2
    float4 tt = T[n];
    float  a = A[n];
    float pd = wc[12] + wc[4]*z.x + wc[5]*z.y + wc[6]*z.z + wc[7]*z.w + wc[14]*a;
    float a3 = a + tt.z + wc[13] * q[n] + tt.w * pd;
    out[n] = make_float4(z.x + a3, z.y + a3, z.z + a3, z.w + a3);
}

// ---------------------------------------------------------------------------
// PDL launch helper
// ---------------------------------------------------------------------------
template <typename... Args>
static void launch_pdl(void (*kern)(Args...), dim3 grid, dim3 block,
                       Args... args) {
    cudaLaunchAttribute attr[1];
    attr[0].id = cudaLaunchAttributeProgrammaticStreamSerialization;
    attr[0].val.programmaticStreamSerializationAllowed = 1;
    cudaLaunchConfig_t cfg = {};
    cfg.gridDim = grid;
    cfg.blockDim = block;
    cfg.dynamicSmemBytes = 0;
    cfg.stream = 0;
    cfg.attrs = attr;
    cfg.numAttrs = 1;
    cudaLaunchKernelEx(&cfg, kern, args...);
}

// ---------------------------------------------------------------------------
extern "C" void kernel_launch(void* const* d_in, const int* in_sizes, int n_in,
                              void* d_out, int out_size) {
    const float* z    = (const float*)d_in[0];
    const float* r    = (const float*)d_in[1];
    const float* rhat = (const float*)d_in[2];
    const float* W    = (const float*)d_in[3];
    const float* b    = (const float*)d_in[4];
    const int*   src  = (const int*)d_in[5];
    const int*   dst  = (const int*)d_in[6];
    float* out = (float*)d_out;

    float4 *T; float *A, *q1, *q2;
    cudaGetSymbolAddress((void**)&T,  g_T);
    cudaGetSymbolAddress((void**)&A,  g_A);
    cudaGetSymbolAddress((void**)&q1, g_q1);
    cudaGetSymbolAddress((void**)&q2, g_q2);

    const dim3 blk(256);
    const dim3 NODE_GRID((N_NODES + 255) / 256);
    const dim3 EDGE_GRID((N_EDGES / 4 + 255) / 256);

    init_kernel<<<NODE_GRID, blk>>>(W, b, T);

    launch_pdl(heavy_edge_kernel, EDGE_GRID, blk,
               (const int4*)src, (const int4*)dst,
               (const float4*)r, (const float4*)rhat,
               (const float4*)z, T);

    launch_pdl(node0_kernel, NODE_GRID, blk,
               (const float4*)z, (const float4*)T, A, q1, (float4*)out);

    launch_pdl(light_edge_kernel, EDGE_GRID, blk,
               (const int4*)src, (const int4*)dst, (const float*)A, q1);

    launch_pdl(node_update1_kernel, NODE_GRID, blk,
               (const float4*)z, (const float4*)T, (const float*)q1, A, q2);

    launch_pdl(light_edge_kernel, EDGE_GRID, blk,
               (const int4*)src, (const int4*)dst, (const float*)A, q2);

    launch_pdl(node_update2_final_kernel, NODE_GRID, blk,
               (const float4*)z, (const float4*)T, (const float*)q2,
               (const float*)A, (float4*)out);
}

// round 14
// speedup vs baseline: 1.4444x; 1.4444x over previous
#include <cuda_runtime.h>
#include <cuda_bf16.h>
#include <cstdint>

#define N_NODES 200000
#define N_EDGES 6400000
#define N_LAYERS 3

// Scratch (no cudaMalloc allowed)
__device__ float4 g_T[N_NODES];    // (t0, t1, t2, deg) accumulators
__device__ float  g_A[N_NODES];    // current per-node cumulative scalar
__device__ float  g_q1[N_NODES];   // M @ A_1
__device__ float  g_q2[N_NODES];   // M @ A_2
// per-layer 16 floats: [0..11]=W row, [12]=b, [13]=sA=sum(w[0:4]), [14]=sB=sum(w[4:8])
__device__ float  g_wc[N_LAYERS * 16];

// PDL primitives
__device__ __forceinline__ void pdl_wait() {
    asm volatile("griddepcontrol.wait;" ::: "memory");
}
__device__ __forceinline__ void pdl_trigger() {
    asm volatile("griddepcontrol.launch_dependents;" ::: "memory");
}

// ---------------------------------------------------------------------------
// 1. init: zero T; block 0 also computes per-layer weight constants.
//    Early trigger: lets heavy_edge ramp + stream loads overlap the zeroing
//    tail (heavy_edge's wait still orders its REDs after init completion of
//    all CTAs' triggers, which come after their stores).
// ---------------------------------------------------------------------------
__global__ void init_kernel(const float* __restrict__ W,
                            const float* __restrict__ b,
                            float4* __restrict__ T) {
    int n = blockIdx.x * blockDim.x + threadIdx.x;
    if (blockIdx.x == 0 && threadIdx.x < N_LAYERS) {
        int i = threadIdx.x;
        float sA = 0.f, sB = 0.f;
        #pragma unroll
        for (int j = 0; j < 12; j++) {
            float w = W[i * 12 + j];
            g_wc[i * 16 + j] = w;
            if (j < 4)       sA += w;
            else if (j < 8)  sB += w;
        }
        g_wc[i * 16 + 12] = b[i];
        g_wc[i * 16 + 13] = sA;
        g_wc[i * 16 + 14] = sB;
    }
    if (n < N_NODES)
        T[n] = make_float4(0.f, 0.f, 0.f, 0.f);
    pdl_trigger();
}

// ---------------------------------------------------------------------------
__device__ __forceinline__ void red_add_v4(float4* ptr, float a, float b,
                                           float c, float d) {
    asm volatile("red.global.add.v4.f32 [%0], {%1, %2, %3, %4};"
                 :: "l"(__cvta_generic_to_global(ptr)),
                    "f"(a), "f"(b), "f"(c), "f"(d)
                 : "memory");
}

// ---------------------------------------------------------------------------
// 2. ONE heavy edge pass for all 3 layers, 4 edges per thread:
//    T[dst] += ( ws_l.z0[src] + w_geo_l.(r,rhat)  for l=0..2 , 1 )
//    Input loads hoisted above pdl_wait. NO explicit trigger: the following
//    node kernel must wait for FULL completion (prevents cascade overlap of
//    LTS-bound edge passes — round-9 lesson).
// ---------------------------------------------------------------------------
__global__ void __launch_bounds__(256)
heavy_edge_kernel(const int4* __restrict__ src4,
                  const int4* __restrict__ dst4,
                  const float4* __restrict__ r4,
                  const float4* __restrict__ rhat4,
                  const float4* __restrict__ z0,
                  float4* __restrict__ T) {
    int t = blockIdx.x * blockDim.x + threadIdx.x;   // grid is exact: no OOB

    int4   s  = __ldcs(src4 + t);
    int4   d  = __ldcs(dst4 + t);
    float4 r  = __ldcs(r4   + t);
    float4 h0 = __ldcs(rhat4 + 3 * t + 0);
    float4 h1 = __ldcs(rhat4 + 3 * t + 1);
    float4 h2 = __ldcs(rhat4 + 3 * t + 2);

    float4 zs0 = __ldg(&z0[s.x]);
    float4 zs1 = __ldg(&z0[s.y]);
    float4 zs2 = __ldg(&z0[s.z]);
    float4 zs3 = __ldg(&z0[s.w]);

    pdl_wait();   // init has zeroed T and written g_wc

    float rr[4]    = {r.x, r.y, r.z, r.w};
    float rh[4][3] = {{h0.x, h0.y, h0.z}, {h0.w, h1.x, h1.y},
                      {h1.z, h1.w, h2.x}, {h2.y, h2.z, h2.w}};
    float4 zs[4]   = {zs0, zs1, zs2, zs3};
    int    dd[4]   = {d.x, d.y, d.z, d.w};

    float tv[4][3];
    #pragma unroll
    for (int l = 0; l < N_LAYERS; l++) {
        const float* wc = g_wc + l * 16;
        float w0 = wc[0], w1 = wc[1], w2 = wc[2], w3 = wc[3];
        float w8 = wc[8], w9 = wc[9], wa = wc[10], wb = wc[11];
        #pragma unroll
        for (int e = 0; e < 4; e++) {
            tv[e][l] = w0 * zs[e].x + w1 * zs[e].y + w2 * zs[e].z + w3 * zs[e].w
                     + w8 * rr[e] + w9 * rh[e][0] + wa * rh[e][1] + wb * rh[e][2];
        }
    }

    #pragma unroll
    for (int e = 0; e < 4; e++)
        red_add_v4(&T[dd[e]], tv[e][0], tv[e][1], tv[e][2], 1.f);
    // no pdl_trigger: implicit at kernel completion
}

// ---------------------------------------------------------------------------
// 3. Light edge pass, 4 edges per thread: q[dst] += A[src]
//    src/dst stream loads hoisted above wait; no explicit trigger.
// ---------------------------------------------------------------------------
__global__ void __launch_bounds__(256)
light_edge_kernel(const int4* __restrict__ src4,
                  const int4* __restrict__ dst4,
                  const float* __restrict__ A,
                  float* __restrict__ q) {
    int t = blockIdx.x * blockDim.x + threadIdx.x;   // grid is exact: no OOB

    int4 s = __ldcs(src4 + t);
    int4 d = __ldcs(dst4 + t);

    pdl_wait();   // A and zeroed q come from the preceding node kernel

    float a0 = __ldg(&A[s.x]);
    float a1 = __ldg(&A[s.y]);
    float a2 = __ldg(&A[s.z]);
    float a3 = __ldg(&A[s.w]);

    atomicAdd(&q[d.x], a0);
    atomicAdd(&q[d.y], a1);
    atomicAdd(&q[d.z], a2);
    atomicAdd(&q[d.w], a3);
    // no pdl_trigger: implicit at kernel completion
}

// ---------------------------------------------------------------------------
// 4. Node update layer 0: A1 = t0 + deg*(b0 + wd0.z0)   (A0 = 0, q0 = 0)
//    Also zeroes q1 and writes out_x = z0. Early trigger after stores so the
//    next light pass ramps under this kernel's tail.
// ---------------------------------------------------------------------------
__global__ void node0_kernel(const float4* __restrict__ z0,
                             const float4* __restrict__ T,
                             float* __restrict__ A,
                             float* __restrict__ q1,
                             float4* __restrict__ out) {
    int n = blockIdx.x * blockDim.x + threadIdx.x;
    bool ok = (n < N_NODES);
    float4 z = make_float4(0.f, 0.f, 0.f, 0.f);
    if (ok) z = z0[n];
    pdl_wait();   // T from heavy pass (full completion)
    if (ok) {
        const float* wc = g_wc;  // layer 0
        float4 tt = T[n];
        float pd = wc[12] + wc[4]*z.x + wc[5]*z.y + wc[6]*z.z + wc[7]*z.w;
        A[n] = tt.x + tt.w * pd;
        q1[n] = 0.f;
        out[N_NODES + n] = z;     // x output
    }
    pdl_trigger();
}

// ---------------------------------------------------------------------------
// 5. Node update layer 1: A2 = A1 + t1 + sA1*q1 + deg*(b1 + wd1.z0 + sB1*A1)
//    Also zeroes q2. Early trigger.
// ---------------------------------------------------------------------------
__global__ void node_update1_kernel(const float4* __restrict__ z0,
                                    const float4* __restrict__ T,
                                    const float* __restrict__ q,
                                    float* __restrict__ A,
                                    float* __restrict__ q2) {
    int n = blockIdx.x * blockDim.x + threadIdx.x;
    bool ok = (n < N_NODES);
    float4 z = make_float4(0.f, 0.f, 0.f, 0.f);
    if (ok) z = z0[n];
    pdl_wait();   // q1 from light pass 1 (full completion)
    if (ok) {
        const float* wc = g_wc + 16;  // layer 1
        float4 tt = T[n];
        float  a = A[n];
        float pd = wc[12] + wc[4]*z.x + wc[5]*z.y + wc[6]*z.z + wc[7]*z.w + wc[14]*a;
        A[n] = a + tt.y + wc[13] * q[n] + tt.w * pd;
        q2[n] = 0.f;
    }
    pdl_trigger();
}

// ---------------------------------------------------------------------------
// 6. Node update layer 2 + finalize:
//    A3 = A2 + t2 + sA2*q2 + deg*(b2 + wd2.z0 + sB2*A2);  out_z = z0 + A3
// ---------------------------------------------------------------------------
__global__ void node_update2_final_kernel(const float4* __restrict__ z0,
                                          const float4* __restrict__ T,
                                          const float* __restrict__ q,
                                          const float* __restrict__ A,
                                          float4* __restrict__ out) {
    int n = blockIdx.x * blockDim.x + threadIdx.x;
    bool ok = (n < N_NODES);
    float4 z = make_float4(0.f, 0.f, 0.f, 0.f);
    if (ok) z = z0[n];
    pdl_wait();   // q2 from light pass 2 (full completion)
    if (!ok) return;
    const float* wc = g_wc + 32;  // layer 2
    float4 tt = T[n];
    float  a = A[n];
    float pd = wc[12] + wc[4]*z.x + wc[5]*z.y + wc[6]*z.z + wc[7]*z.w + wc[14]*a;
    float a3 = a + tt.z + wc[13] * q[n] + tt.w * pd;
    out[n] = make_float4(z.x + a3, z.y + a3, z.z + a3, z.w + a3);
}

// ---------------------------------------------------------------------------
// PDL launch helper
// ---------------------------------------------------------------------------
template <typename... Args>
static void launch_pdl(void (*kern)(Args...), dim3 grid, dim3 block,
                       Args... args) {
    cudaLaunchAttribute attr[1];
    attr[0].id = cudaLaunchAttributeProgrammaticStreamSerialization;
    attr[0].val.programmaticStreamSerializationAllowed = 1;
    cudaLaunchConfig_t cfg = {};
    cfg.gridDim = grid;
    cfg.blockDim = block;
    cfg.dynamicSmemBytes = 0;
    cfg.stream = 0;
    cfg.attrs = attr;
    cfg.numAttrs = 1;
    cudaLaunchKernelEx(&cfg, kern, args...);
}

// ---------------------------------------------------------------------------
extern "C" void kernel_launch(void* const* d_in, const int* in_sizes, int n_in,
                              void* d_out, int out_size) {
    const float* z    = (const float*)d_in[0];
    const float* r    = (const float*)d_in[1];
    const float* rhat = (const float*)d_in[2];
    const float* W    = (const float*)d_in[3];
    const float* b    = (const float*)d_in[4];
    const int*   src  = (const int*)d_in[5];
    const int*   dst  = (const int*)d_in[6];
    float* out = (float*)d_out;

    float4 *T; float *A, *q1, *q2;
    cudaGetSymbolAddress((void**)&T,  g_T);
    cudaGetSymbolAddress((void**)&A,  g_A);
    cudaGetSymbolAddress((void**)&q1, g_q1);
    cudaGetSymbolAddress((void**)&q2, g_q2);

    const dim3 blk(256);
    const dim3 NODE_GRID((N_NODES + 255) / 256);
    const dim3 EDGE_GRID(N_EDGES / 4 / 256);   // exact: 6250

    init_kernel<<<NODE_GRID, blk>>>(W, b, T);

    launch_pdl(heavy_edge_kernel, EDGE_GRID, blk,
               (const int4*)src, (const int4*)dst,
               (const float4*)r, (const float4*)rhat,
               (const float4*)z, T);

    launch_pdl(node0_kernel, NODE_GRID, blk,
               (const float4*)z, (const float4*)T, A, q1, (float4*)out);

    launch_pdl(light_edge_kernel, EDGE_GRID, blk,
               (const int4*)src, (const int4*)dst, (const float*)A, q1);

    launch_pdl(node_update1_kernel, NODE_GRID, blk,
               (const float4*)z, (const float4*)T, (const float*)q1, A, q2);

    launch_pdl(light_edge_kernel, EDGE_GRID, blk,
               (const int4*)src, (const int4*)dst, (const float*)A, q2);

    launch_pdl(node_update2_final_kernel, NODE_GRID, blk,
               (const float4*)z, (const float4*)T, (const float*)q2,
               (const float*)A, (float4*)out);
}